// round 8
// baseline (speedup 1.0000x reference)
#include <cuda_runtime.h>
#include <cuda_bf16.h>

// Single-launch top-10% mask. 296 co-resident blocks (2/SM enforced via
// __launch_bounds__(512,2)), device-wide phase-counting barriers (replay-safe:
// phase var is monotone, count self-resets).
// P0: 1/16 sample -> 2^17-bin global fine histogram (2^13-key bins).
// P1: chunk sums (128 x 1024-bin chunks). P2: block0/matrix -> band [Tlo,Thi)
//     at fine-bin granularity, +-2500-sample margins (8 sigma).
// P3: fused full pass: provisional mask (k>=Tlo), hi count (k>=Thi), band
//     candidate compaction (~100K/matrix).
// P4/P5: two narrowing stages over candidates (2048-bin global hists, scans
//     replicated per block) -> exact threshold key T + tie residual z.
// P6: final candidate pass (k<T -> 0, collect k==T); block0 does stable
//     argsort tie fixup (zero first z equals by ascending flat index).
// Any band infeasibility is DETECTED (hiCnt/keep checks) -> single-block
// rescue recomputes everything exactly (correctness unconditional).
// All global state self-cleans at the end for graph replays.

#define SHIFTF   13
#define NBF      (1u << 17)
#define CHUNK    1024
#define NCHUNK   128
#define NST      2048
#define CAND_CAP (1u << 19)
#define BLK_CAP  2048
#define EQ_CAP   4096
#define TPB      512
#define NBM      148
#define GRID     (2 * NBM)

__device__ unsigned g_fine[2][NBF];
__device__ unsigned g_csum[2][NCHUNK];
__device__ unsigned g_Tlo[2], g_Thi[2];
__device__ unsigned g_st1[2][NST];
__device__ unsigned g_st2[2][NST];
__device__ unsigned g_cand_idx[2][CAND_CAP];
__device__ unsigned g_cand_key[2][CAND_CAP];
__device__ unsigned g_cand_cnt[2];
__device__ unsigned g_hiCnt[2];
__device__ unsigned g_fail[2];
__device__ unsigned g_eq[2][EQ_CAP];
__device__ unsigned g_eq_cnt[2];
__device__ unsigned g_bcount[8];
__device__ unsigned g_bphase[8];   // monotone across replays; never reset

__device__ __forceinline__ unsigned abskey(float v) {
    return __float_as_uint(v) & 0x7FFFFFFFu;
}

// Device-wide barrier, one slot per use-site per launch. Phase-counting:
// count self-resets, phase increments monotonically (replay-safe).
__device__ __forceinline__ void gbar(int slot) {
    __syncthreads();
    if (threadIdx.x == 0) {
        unsigned ph = *(volatile unsigned*)&g_bphase[slot];
        __threadfence();
        if (atomicAdd(&g_bcount[slot], 1u) == (unsigned)GRID - 1u) {
            g_bcount[slot] = 0;
            __threadfence();
            atomicAdd(&g_bphase[slot], 1u);
        } else {
            while (*(volatile unsigned*)&g_bphase[slot] == ph) __nanosleep(64);
        }
        __threadfence();
    }
    __syncthreads();
}

// All-512-thread inclusive scan of sh[0..511] (caller inits + syncs).
__device__ __forceinline__ void scan512(unsigned* sh) {
    const int t = threadIdx.x;
    for (int off = 1; off < TPB; off <<= 1) {
        unsigned x = (t >= off) ? sh[t - off] : 0u;
        __syncthreads();
        sh[t] += x;
        __syncthreads();
    }
}

// Whole-block: fine bin containing ascending sample rank (S - C).
__device__ unsigned find_cut(int m, unsigned C, unsigned* sh) {
    __shared__ unsigned f_chunk, f_rank, f_bin;
    const int t = threadIdx.x;
    unsigned v = (t < NCHUNK) ? g_csum[m][t] : 0u;
    __syncthreads();
    sh[t] = (t < NCHUNK) ? v : 0u;
    __syncthreads();
    for (int off = 1; off < NCHUNK; off <<= 1) {
        unsigned x = (t < NCHUNK && t >= off) ? sh[t - off] : 0u;
        __syncthreads();
        if (t < NCHUNK) sh[t] += x;
        __syncthreads();
    }
    unsigned S = sh[NCHUNK - 1];
    unsigned r = (S >= C) ? (S - C) : 0u;
    if (t < NCHUNK) {
        unsigned incl = sh[t], excl = incl - v;
        if (excl <= r && r < incl) { f_chunk = t; f_rank = r - excl; }
    }
    __syncthreads();
    unsigned ch = f_chunk, rr = f_rank;
    unsigned b0 = g_fine[m][ch * CHUNK + t * 2];
    unsigned b1 = g_fine[m][ch * CHUNK + t * 2 + 1];
    unsigned sum = b0 + b1;
    __syncthreads();
    sh[t] = sum;
    __syncthreads();
    scan512(sh);
    {
        unsigned run = sh[t] - sum;
        if (run <= rr && rr < run + b0) f_bin = ch * CHUNK + t * 2;
        else if (run + b0 <= rr && rr < run + b0 + b1) f_bin = ch * CHUNK + t * 2 + 1;
    }
    __syncthreads();
    unsigned b = f_bin;
    __syncthreads();
    return b;
}

// Single-block exact rescue (only on detected band failure).
__device__ void rescue_block(const float* __restrict__ in, float* __restrict__ dst,
                             int n, unsigned target_top, unsigned* sh) {
    __shared__ unsigned r_lo, r_span, r_rank;
    const int t = threadIdx.x;
    if (t == 0) { r_lo = 0; r_span = 1u << 30; r_rank = (unsigned)n - target_top; }
    __syncthreads();
    while (r_span > 1) {
        unsigned lo = r_lo, span = r_span;
        unsigned s = (span > (unsigned)NST) ? (unsigned)(32 - __clz(span - 1) - 11) : 0u;
        for (int i = t; i < NST; i += TPB) sh[i] = 0;
        __syncthreads();
        for (int i = t; i < n; i += TPB) {
            unsigned d = abskey(in[i]) - lo;
            if (d < span) atomicAdd(&sh[d >> s], 1u);
        }
        __syncthreads();
        if (t == 0) {
            unsigned rank = r_rank, run = 0;
            for (int i = 0; i < NST; i++) {
                unsigned cc = sh[i];
                if (rank < run + cc) { r_lo = lo + ((unsigned)i << s); r_span = 1u << s; r_rank = rank - run; break; }
                run += cc;
            }
        }
        __syncthreads();
    }
    unsigned T = r_lo, z = r_rank;
    for (int i = t; i < n; i += TPB) {
        unsigned k = abskey(in[i]);
        if (k != T) dst[i] = (k > T) ? 1.0f : 0.0f;
    }
    __syncthreads();
    if (t == 0) {
        unsigned seen = 0;
        for (int i = 0; i < n; i++)
            if (abskey(in[i]) == T) { dst[i] = (seen < z) ? 0.0f : 1.0f; seen++; }
    }
    __syncthreads();
}

__global__ void __launch_bounds__(TPB, 2)
mask_kernel(const float4* __restrict__ A, const float4* __restrict__ B,
            float4* __restrict__ out, int n4, int n4s,
            unsigned target_top, unsigned C_lo, unsigned C_hi) {
    __shared__ unsigned sh[NST];
    __shared__ unsigned sidx[BLK_CAP];
    __shared__ unsigned skey[BLK_CAP];
    __shared__ unsigned sv0, sv1, sv2;
    const int m = blockIdx.x & 1;
    const int bl = blockIdx.x >> 1;
    const int t = threadIdx.x;
    const int n = n4 * 4;
    const float4* __restrict__ in4 = m ? B : A;
    float4* __restrict__ dst4 = out + (size_t)m * (size_t)n4;
    float* __restrict__ dst1 = (float*)dst4;
    const int stride = NBM * TPB;

    // ---- P0: sample 1/16 into fine global histogram ----
    for (int i = bl * TPB + t; i < n4s; i += stride) {
        float4 v = in4[i];
        atomicAdd(&g_fine[m][abskey(v.x) >> SHIFTF], 1u);
        atomicAdd(&g_fine[m][abskey(v.y) >> SHIFTF], 1u);
        atomicAdd(&g_fine[m][abskey(v.z) >> SHIFTF], 1u);
        atomicAdd(&g_fine[m][abskey(v.w) >> SHIFTF], 1u);
    }
    gbar(0);

    // ---- P1: chunk sums (block bl handles chunk bl) ----
    if (bl < NCHUNK) {
        unsigned v = g_fine[m][bl * CHUNK + t * 2] + g_fine[m][bl * CHUNK + t * 2 + 1];
        for (int off = 16; off > 0; off >>= 1) v += __shfl_down_sync(0xFFFFFFFFu, v, off);
        if ((t & 31) == 0) sh[t >> 5] = v;
        __syncthreads();
        if (t < 16) {
            v = sh[t];
            for (int off = 8; off > 0; off >>= 1) v += __shfl_down_sync(0xFFFFu, v, off);
            if (t == 0) g_csum[m][bl] = v;
        }
    }
    gbar(1);

    // ---- P2: designated block computes band [Tlo, Thi) ----
    if (bl == 0) {
        unsigned binA = find_cut(m, C_hi, sh);
        unsigned binB = find_cut(m, C_lo, sh);
        if (t == 0) {
            g_Tlo[m] = binA << SHIFTF;
            g_Thi[m] = (binB + 1u) << SHIFTF;
        }
    }
    gbar(2);
    const unsigned Tlo = *(volatile unsigned*)&g_Tlo[m];
    const unsigned Thi = *(volatile unsigned*)&g_Thi[m];

    // ---- P3: fused full pass ----
    if (t == 0) { sv0 = 0; sv2 = 0; }   // sv0 = cand cnt, sv2 = hi cnt
    __syncthreads();
    {
        unsigned hi = 0;
        int i0 = bl * TPB + t;
        for (int i = i0; i < n4; i += 2 * stride) {
            int i2 = i + stride;
            float4 v0 = in4[i];
            float4 v1 = (i2 < n4) ? in4[i2] : make_float4(0.f, 0.f, 0.f, 0.f);
            float4 r0, r1;
            unsigned b0 = ((unsigned)i) << 2;
            unsigned b1 = ((unsigned)i2) << 2;
            unsigned k;

            k = abskey(v0.x); r0.x = (k >= Tlo) ? 1.0f : 0.0f; hi += (k >= Thi);
            if (k >= Tlo && k < Thi) { unsigned p = atomicAdd(&sv0, 1u); if (p < BLK_CAP) { sidx[p] = b0;     skey[p] = k; } }
            k = abskey(v0.y); r0.y = (k >= Tlo) ? 1.0f : 0.0f; hi += (k >= Thi);
            if (k >= Tlo && k < Thi) { unsigned p = atomicAdd(&sv0, 1u); if (p < BLK_CAP) { sidx[p] = b0 + 1; skey[p] = k; } }
            k = abskey(v0.z); r0.z = (k >= Tlo) ? 1.0f : 0.0f; hi += (k >= Thi);
            if (k >= Tlo && k < Thi) { unsigned p = atomicAdd(&sv0, 1u); if (p < BLK_CAP) { sidx[p] = b0 + 2; skey[p] = k; } }
            k = abskey(v0.w); r0.w = (k >= Tlo) ? 1.0f : 0.0f; hi += (k >= Thi);
            if (k >= Tlo && k < Thi) { unsigned p = atomicAdd(&sv0, 1u); if (p < BLK_CAP) { sidx[p] = b0 + 3; skey[p] = k; } }
            dst4[i] = r0;

            if (i2 < n4) {
                k = abskey(v1.x); r1.x = (k >= Tlo) ? 1.0f : 0.0f; hi += (k >= Thi);
                if (k >= Tlo && k < Thi) { unsigned p = atomicAdd(&sv0, 1u); if (p < BLK_CAP) { sidx[p] = b1;     skey[p] = k; } }
                k = abskey(v1.y); r1.y = (k >= Tlo) ? 1.0f : 0.0f; hi += (k >= Thi);
                if (k >= Tlo && k < Thi) { unsigned p = atomicAdd(&sv0, 1u); if (p < BLK_CAP) { sidx[p] = b1 + 1; skey[p] = k; } }
                k = abskey(v1.z); r1.z = (k >= Tlo) ? 1.0f : 0.0f; hi += (k >= Thi);
                if (k >= Tlo && k < Thi) { unsigned p = atomicAdd(&sv0, 1u); if (p < BLK_CAP) { sidx[p] = b1 + 2; skey[p] = k; } }
                k = abskey(v1.w); r1.w = (k >= Tlo) ? 1.0f : 0.0f; hi += (k >= Thi);
                if (k >= Tlo && k < Thi) { unsigned p = atomicAdd(&sv0, 1u); if (p < BLK_CAP) { sidx[p] = b1 + 3; skey[p] = k; } }
                dst4[i2] = r1;
            }
        }
        for (int off = 16; off > 0; off >>= 1) hi += __shfl_down_sync(0xFFFFFFFFu, hi, off);
        if ((t & 31) == 0 && hi) atomicAdd(&sv2, hi);
        __syncthreads();
        if (t == 0) {
            if (sv2) atomicAdd(&g_hiCnt[m], sv2);
            unsigned c = sv0;
            if (c > BLK_CAP) { atomicExch(&g_fail[m], 1u); c = BLK_CAP; }
            sv0 = c;
            sv1 = atomicAdd(&g_cand_cnt[m], c);
        }
        __syncthreads();
        unsigned c = sv0, bpos = sv1;
        for (unsigned p = t; p < c; p += TPB) {
            unsigned gp = bpos + p;
            if (gp < CAND_CAP) { g_cand_idx[m][gp] = sidx[p]; g_cand_key[m][gp] = skey[p]; }
        }
    }
    gbar(3);

    // ---- refinement setup (replicated per block, deterministic) ----
    unsigned cnt_real = *(volatile unsigned*)&g_cand_cnt[m];
    unsigned cnt = min(cnt_real, CAND_CAP);
    unsigned hic = *(volatile unsigned*)&g_hiCnt[m];
    bool bad = (*(volatile unsigned*)&g_fail[m] != 0) || (cnt_real > CAND_CAP) ||
               (hic > target_top) || (target_top - hic > cnt);
    bool zerokeep = false;
    unsigned lo = Tlo, span = Thi - Tlo, rank = 0;
    if (!bad) {
        unsigned keep = target_top - hic;
        if (keep == 0) zerokeep = true;
        else rank = cnt - keep;
    }
    if (!bad && !zerokeep && span > (1u << 22)) bad = true;
    const unsigned* __restrict__ keys = g_cand_key[m];
    const unsigned* __restrict__ idxs = g_cand_idx[m];
    bool need1 = !bad && !zerokeep && (span > 1);
    unsigned s1 = 0;

    // ---- P4: stage-1 histogram over candidates ----
    if (need1) {
        s1 = (span > (unsigned)NST) ? (unsigned)(32 - __clz(span - 1) - 11) : 0u;
        for (int i = t; i < NST; i += TPB) sh[i] = 0;
        __syncthreads();
        for (unsigned c = bl * TPB + t; c < cnt; c += stride) {
            unsigned d = keys[c] - lo;
            if (d < span) atomicAdd(&sh[d >> s1], 1u);
        }
        __syncthreads();
        for (int i = t; i < NST; i += TPB) {
            unsigned v = sh[i];
            if (v) atomicAdd(&g_st1[m][i], v);
        }
    }
    gbar(4);

    // ---- P5: replicated scan of st1; then stage-2 histogram ----
    bool need2 = false;
    if (need1) {
        unsigned loc[4], sum = 0;
        #pragma unroll
        for (int i = 0; i < 4; i++) { loc[i] = g_st1[m][t * 4 + i]; sum += loc[i]; }
        __syncthreads();
        sh[t] = sum;
        __syncthreads();
        scan512(sh);
        unsigned run = sh[t] - sum;
        #pragma unroll
        for (int i = 0; i < 4; i++) {
            if (run <= rank && rank < run + loc[i]) { sv0 = (unsigned)(t * 4 + i); sv1 = rank - run; }
            run += loc[i];
        }
        __syncthreads();
        lo += sv0 << s1;
        span = 1u << s1;
        rank = sv1;
        __syncthreads();
        need2 = (span > 1);
        if (need2) {
            for (int i = t; i < NST; i += TPB) sh[i] = 0;
            __syncthreads();
            for (unsigned c = bl * TPB + t; c < cnt; c += stride) {
                unsigned d = keys[c] - lo;
                if (d < span) atomicAdd(&sh[d], 1u);
            }
            __syncthreads();
            for (int i = t; i < NST; i += TPB) {
                unsigned v = sh[i];
                if (v) atomicAdd(&g_st2[m][i], v);
            }
        }
    }
    gbar(5);

    // ---- P6: resolve exact T,z; final candidate pass ----
    unsigned T = 0, z = 0;
    if (!bad) {
        if (zerokeep) { T = 0x7FFFFFFFu; z = 0; }       // above every key (< 2^30)
        else if (!need2) { T = lo; z = rank; }
        else {
            unsigned loc[4], sum = 0;
            #pragma unroll
            for (int i = 0; i < 4; i++) {
                unsigned ix = (unsigned)(t * 4 + i);
                loc[i] = (ix < span) ? g_st2[m][ix] : 0u;
                sum += loc[i];
            }
            __syncthreads();
            sh[t] = sum;
            __syncthreads();
            scan512(sh);
            unsigned run = sh[t] - sum;
            #pragma unroll
            for (int i = 0; i < 4; i++) {
                if (run <= rank && rank < run + loc[i]) { sv0 = (unsigned)(t * 4 + i); sv1 = rank - run; }
                run += loc[i];
            }
            __syncthreads();
            T = lo + sv0;
            z = sv1;
            __syncthreads();
        }
        for (unsigned c = bl * TPB + t; c < cnt; c += stride) {
            unsigned k = keys[c];
            if (k < T) {
                dst1[idxs[c]] = 0.0f;
            } else if (k == T) {
                unsigned p = atomicAdd(&g_eq_cnt[m], 1u);
                if (p < EQ_CAP) g_eq[m][p] = idxs[c];
            }
        }
    }
    gbar(6);

    // ---- P7: tie fixup / rescue (block 0 of each matrix) + cleanup ----
    if (bl == 0) {
        unsigned eq = *(volatile unsigned*)&g_eq_cnt[m];
        if (!bad && eq > EQ_CAP) bad = true;
        if (!bad) {
            for (unsigned e = t; e < eq; e += TPB) {
                unsigned idx = g_eq[m][e];
                unsigned c2 = 0;
                for (unsigned q = 0; q < eq; q++) c2 += (g_eq[m][q] < idx) ? 1u : 0u;
                if (c2 < z) dst1[idx] = 0.0f;
            }
        } else {
            rescue_block((const float*)in4, dst1, n, target_top, sh);
        }
        __syncthreads();
        if (t == 0) {
            g_cand_cnt[m] = 0; g_hiCnt[m] = 0; g_fail[m] = 0; g_eq_cnt[m] = 0;
        }
    }
    // array cleanup for next replay (no one reads these anymore this launch)
    for (unsigned i = bl * TPB + t; i < NBF; i += (unsigned)stride) g_fine[m][i] = 0;
    for (unsigned i = bl * TPB + t; i < (unsigned)NST; i += (unsigned)stride) {
        g_st1[m][i] = 0;
        g_st2[m][i] = 0;
    }
    if (bl == 1 && t < NCHUNK) g_csum[m][t] = 0;
}

extern "C" void kernel_launch(void* const* d_in, const int* in_sizes, int n_in,
                              void* d_out, int out_size) {
    const float* A = (const float*)d_in[0];
    const float* B = (const float*)d_in[1];
    float* out = (float*)d_out;

    int n = in_sizes[0];
    int n4 = n / 4;
    int n4s = n4 / 16;                                  // 1/16 sample (prefix)
    unsigned j = (unsigned)((1.0 - 0.1) * (double)n);   // mirrors int((1-k)*n)
    unsigned target_top = (unsigned)n - j;
    unsigned ns = (unsigned)n4s * 4u;
    unsigned k_s = (unsigned)((double)target_top * (double)ns / (double)n);
    unsigned margin = 2500u;                            // ~8 sigma
    unsigned C_hi = k_s + margin; if (C_hi > ns) C_hi = ns;
    unsigned C_lo = (k_s > margin) ? (k_s - margin) : 1u;

    mask_kernel<<<GRID, TPB>>>((const float4*)A, (const float4*)B, (float4*)out,
                               n4, n4s, target_top, C_lo, C_hi);
}